// round 2
// baseline (speedup 1.0000x reference)
#include <cuda_runtime.h>

// ---------------- problem constants ----------------
#define NN   10000      // nodes
#define DIN  1716       // input dim
#define DE1  2000       // enc1 dim
#define DE2  256        // enc2 dim
#define DZ   128        // latent dim (== ATT_H)
#define NE   100000     // edges
#define NP   200000     // pairs

// output layout (float32 concat of the reference tuple)
#define OFF_EMB1  0ull
#define OFF_BETA  1280000ull
#define OFF_XBAR  1300000ull
#define OFF_PAIRS 18460000ull
#define OFF_LAB   44060000ull

// ---------------- device scratch ----------------
__device__ float g_tra1[NN * DE1];
__device__ float g_tra2[NN * DE2];
__device__ float g_z   [NN * DZ ];
__device__ float g_dec1[NN * DE2];
__device__ float g_dec2[NN * DE1];
__device__ float g_s1  [NN * DE1];
__device__ float g_h1  [NN * DE1];
__device__ float g_s2  [NN * DE2];
__device__ float g_h2  [NN * DE2];
__device__ float g_s3  [NN * DZ ];
__device__ float g_h3  [NN * DZ ];
__device__ float g_emb1[NN * DZ ];
__device__ int   g_rowptr[NN + 1];

// ---------------- SGEMM: C = op(A) @ B (+bias) (+relu) ----------------
// A: [M,K] row-major, B: [K,N] row-major, C: [M,N] row-major.
// MIX: op(A) = 0.5*A + 0.5*A2 (SIGMA = 0.5).
template <bool RELU, bool BIAS, bool MIX>
__global__ void __launch_bounds__(256)
sgemm_kernel(int M, int N, int K,
             const float* __restrict__ A, const float* __restrict__ A2,
             const float* __restrict__ B, const float* __restrict__ bias,
             float* __restrict__ C)
{
    constexpr int BM = 128, BN = 128, BK = 8, TM = 8, TN = 8;
    __shared__ float As[BK][BM];
    __shared__ float Bs[BK][BN];

    const int bx = blockIdx.x, by = blockIdx.y;
    const int tid = threadIdx.x;
    const int tcol = tid & 15;        // 0..15
    const int trow = tid >> 4;        // 0..15

    // A-tile load mapping: 128x8 elems, 4 per thread
    const int aRow = tid >> 1;              // 0..127
    const int aCol = (tid & 1) * 4;         // 0 or 4
    // B-tile load mapping: 8x128 elems, 4 per thread
    const int bRow = tid >> 5;              // 0..7
    const int bCol = (tid & 31) * 4;        // 0..124

    float acc[TM][TN];
#pragma unroll
    for (int i = 0; i < TM; i++)
#pragma unroll
        for (int j = 0; j < TN; j++) acc[i][j] = 0.f;

    for (int k0 = 0; k0 < K; k0 += BK) {
#pragma unroll
        for (int i = 0; i < 4; i++) {
            int gr = by * BM + aRow;
            int gc = k0 + aCol + i;
            float v = 0.f;
            if (gr < M && gc < K) {
                size_t idx = (size_t)gr * K + gc;
                v = A[idx];
                if (MIX) v = 0.5f * v + 0.5f * A2[idx];
            }
            As[aCol + i][aRow] = v;
        }
#pragma unroll
        for (int i = 0; i < 4; i++) {
            int gr = k0 + bRow;
            int gc = bx * BN + bCol + i;
            Bs[bRow][bCol + i] = (gr < K && gc < N) ? B[(size_t)gr * N + gc] : 0.f;
        }
        __syncthreads();

#pragma unroll
        for (int kk = 0; kk < BK; kk++) {
            float ar[TM], br[TN];
#pragma unroll
            for (int i = 0; i < TM; i++) ar[i] = As[kk][trow * TM + i];
#pragma unroll
            for (int j = 0; j < TN; j++) br[j] = Bs[kk][tcol * TN + j];
#pragma unroll
            for (int i = 0; i < TM; i++)
#pragma unroll
                for (int j = 0; j < TN; j++) acc[i][j] += ar[i] * br[j];
        }
        __syncthreads();
    }

#pragma unroll
    for (int i = 0; i < TM; i++) {
        int row = by * BM + trow * TM + i;
        if (row >= M) continue;
#pragma unroll
        for (int j = 0; j < TN; j++) {
            int col = bx * BN + tcol * TN + j;
            if (col >= N) continue;
            float v = acc[i][j];
            if (BIAS) v += bias[col];
            if (RELU) v = fmaxf(v, 0.f);
            C[(size_t)row * N + col] = v;
        }
    }
}

// ---------------- sorted-COO -> row_ptr via binary search ----------------
__global__ void build_rowptr_kernel(const int* __restrict__ rows)
{
    int r = blockIdx.x * blockDim.x + threadIdx.x;
    if (r > NN) return;
    int lo = 0, hi = NE;
    while (lo < hi) {
        int mid = (lo + hi) >> 1;
        if (rows[mid] < r) lo = mid + 1; else hi = mid;
    }
    g_rowptr[r] = lo;
}

// ---------------- SpMM (CSR-style, atomic-free) + relu ----------------
__global__ void spmm_relu_kernel(const int* __restrict__ cols,
                                 const float* __restrict__ vals,
                                 const float* __restrict__ sup,
                                 int C, float* __restrict__ out)
{
    int r = blockIdx.y;
    int c = blockIdx.x * blockDim.x + threadIdx.x;
    if (c >= C) return;
    float acc = 0.f;
    int e0 = g_rowptr[r], e1 = g_rowptr[r + 1];
    for (int e = e0; e < e1; e++)
        acc += vals[e] * sup[(size_t)cols[e] * C + c];
    out[(size_t)r * C + c] = fmaxf(acc, 0.f);
}

// ---------------- attention fusion: emb1 + beta ----------------
__global__ void __launch_bounds__(128)
attention_kernel(const float* __restrict__ Wa1, const float* __restrict__ ba1,
                 const float* __restrict__ Wa2, float* __restrict__ out)
{
    int i = blockIdx.x;
    int t = threadIdx.x;           // 0..127
    __shared__ float h3s[DZ], zs[DZ];
    __shared__ float red0[DZ], red1[DZ];
    __shared__ float b0s, b1s;

    h3s[t] = g_h3[(size_t)i * DZ + t];
    zs[t]  = g_z [(size_t)i * DZ + t];
    __syncthreads();

    float s0 = ba1[t], s1 = ba1[t];
    for (int k = 0; k < DZ; k++) {
        float w = Wa1[k * DZ + t];
        s0 += h3s[k] * w;
        s1 += zs[k]  * w;
    }
    float wa2 = Wa2[t];
    red0[t] = tanhf(s0) * wa2;
    red1[t] = tanhf(s1) * wa2;
    __syncthreads();
    for (int s = 64; s > 0; s >>= 1) {
        if (t < s) { red0[t] += red0[t + s]; red1[t] += red1[t + s]; }
        __syncthreads();
    }
    if (t == 0) {
        float w0 = red0[0], w1 = red1[0];
        float m  = fmaxf(w0, w1);
        float e0 = expf(w0 - m), e1 = expf(w1 - m);
        float inv = 1.f / (e0 + e1);
        b0s = e0 * inv; b1s = e1 * inv;
        out[OFF_BETA + (size_t)i * 2 + 0] = b0s;
        out[OFF_BETA + (size_t)i * 2 + 1] = b1s;
    }
    __syncthreads();
    float e = b0s * h3s[t] + b1s * zs[t];
    g_emb1[(size_t)i * DZ + t] = e;
    out[OFF_EMB1 + (size_t)i * DZ + t] = e;
}

// ---------------- pairs: C1/C2 are contiguous halves of `pairs` ----------------
__global__ void pairs_kernel(const int* __restrict__ pair_idx, float* __restrict__ out)
{
    long long idx = (long long)blockIdx.x * blockDim.x + threadIdx.x;
    if (idx >= (long long)NP * DZ) return;
    int p = (int)(idx >> 7);
    int c = (int)(idx & 127);
    int a = pair_idx[2 * p];
    int b = pair_idx[2 * p + 1];
    out[OFF_PAIRS + idx] =
        0.5f * (g_emb1[(size_t)a * DZ + c] + g_emb1[(size_t)b * DZ + c]);
}

// ---------------- labels -> float ----------------
__global__ void labels_kernel(const int* __restrict__ labels, float* __restrict__ out)
{
    int p = blockIdx.x * blockDim.x + threadIdx.x;
    if (p >= NP) return;
    out[OFF_LAB + p] = (float)labels[p];
}

// ---------------- launch helpers ----------------
static inline dim3 gemm_grid(int M, int N)
{
    return dim3((N + 127) / 128, (M + 127) / 128);
}

extern "C" void kernel_launch(void* const* d_in, const int* in_sizes, int n_in,
                              void* d_out, int out_size)
{
    const float* x        = (const float*)d_in[0];
    const int*   adj_rows = (const int*)  d_in[1];
    const int*   adj_cols = (const int*)  d_in[2];
    const float* adj_vals = (const float*)d_in[3];
    const int*   pair_idx = (const int*)  d_in[4];
    const int*   labels   = (const int*)  d_in[5];
    const float* W_enc1 = (const float*)d_in[6];
    const float* b_enc1 = (const float*)d_in[7];
    const float* W_enc2 = (const float*)d_in[8];
    const float* b_enc2 = (const float*)d_in[9];
    const float* W_z    = (const float*)d_in[10];
    const float* b_z    = (const float*)d_in[11];
    const float* W_dec1 = (const float*)d_in[12];
    const float* b_dec1 = (const float*)d_in[13];
    const float* W_dec2 = (const float*)d_in[14];
    const float* b_dec2 = (const float*)d_in[15];
    const float* W_xbar = (const float*)d_in[16];
    const float* b_xbar = (const float*)d_in[17];
    const float* W_g1   = (const float*)d_in[18];
    const float* W_g2   = (const float*)d_in[19];
    const float* W_g3   = (const float*)d_in[20];
    const float* W_a1   = (const float*)d_in[21];
    const float* b_a1   = (const float*)d_in[22];
    const float* W_a2   = (const float*)d_in[23];
    float* out = (float*)d_out;

    float *tra1, *tra2, *z, *dec1, *dec2, *s1, *h1, *s2, *h2, *s3, *h3;
    cudaGetSymbolAddress((void**)&tra1, g_tra1);
    cudaGetSymbolAddress((void**)&tra2, g_tra2);
    cudaGetSymbolAddress((void**)&z,    g_z);
    cudaGetSymbolAddress((void**)&dec1, g_dec1);
    cudaGetSymbolAddress((void**)&dec2, g_dec2);
    cudaGetSymbolAddress((void**)&s1,   g_s1);
    cudaGetSymbolAddress((void**)&h1,   g_h1);
    cudaGetSymbolAddress((void**)&s2,   g_s2);
    cudaGetSymbolAddress((void**)&h2,   g_h2);
    cudaGetSymbolAddress((void**)&s3,   g_s3);
    cudaGetSymbolAddress((void**)&h3,   g_h3);

    // --- autoencoder branch ---
    sgemm_kernel<true,  true,  false><<<gemm_grid(NN, DE1), 256>>>(NN, DE1, DIN, x,    nullptr, W_enc1, b_enc1, tra1);
    sgemm_kernel<true,  true,  false><<<gemm_grid(NN, DE2), 256>>>(NN, DE2, DE1, tra1, nullptr, W_enc2, b_enc2, tra2);
    sgemm_kernel<false, true,  false><<<gemm_grid(NN, DZ ), 256>>>(NN, DZ,  DE2, tra2, nullptr, W_z,    b_z,    z);
    sgemm_kernel<true,  true,  false><<<gemm_grid(NN, DE2), 256>>>(NN, DE2, DZ,  z,    nullptr, W_dec1, b_dec1, dec1);
    sgemm_kernel<true,  true,  false><<<gemm_grid(NN, DE1), 256>>>(NN, DE1, DE2, dec1, nullptr, W_dec2, b_dec2, dec2);
    sgemm_kernel<false, true,  false><<<gemm_grid(NN, DIN), 256>>>(NN, DIN, DE1, dec2, nullptr, W_xbar, b_xbar, out + OFF_XBAR);

    // --- GCN branch ---
    build_rowptr_kernel<<<(NN + 256) / 256, 256>>>(adj_rows);

    sgemm_kernel<false, false, false><<<gemm_grid(NN, DE1), 256>>>(NN, DE1, DIN, x, nullptr, W_g1, nullptr, s1);
    spmm_relu_kernel<<<dim3((DE1 + 255) / 256, NN), 256>>>(adj_cols, adj_vals, s1, DE1, h1);

    sgemm_kernel<false, false, true ><<<gemm_grid(NN, DE2), 256>>>(NN, DE2, DE1, h1, tra1, W_g2, nullptr, s2);
    spmm_relu_kernel<<<dim3((DE2 + 255) / 256, NN), 256>>>(adj_cols, adj_vals, s2, DE2, h2);

    sgemm_kernel<false, false, true ><<<gemm_grid(NN, DZ ), 256>>>(NN, DZ,  DE2, h2, tra2, W_g3, nullptr, s3);
    spmm_relu_kernel<<<dim3((DZ + 255) / 256, NN), 256>>>(adj_cols, adj_vals, s3, DZ, h3);

    // --- attention fusion + outputs ---
    attention_kernel<<<NN, 128>>>(W_a1, b_a1, W_a2, out);

    long long pair_elems = (long long)NP * DZ;
    pairs_kernel<<<(unsigned)((pair_elems + 255) / 256), 256>>>(pair_idx, out);
    labels_kernel<<<(NP + 255) / 256, 256>>>(labels, out);
}

// round 4
// speedup vs baseline: 2.1914x; 2.1914x over previous
#include <cuda_runtime.h>
#include <cuda_bf16.h>
#include <cstdint>

// ---------------- problem constants ----------------
#define NN   10000
#define DIN  1716
#define DE1  2000
#define DE2  256
#define DZ   128
#define NE   100000
#define NP   200000
#define MP   10112      // NN padded to 128

// padded dims (all multiples of 64 -> multiples of BK=32)
#define KP_X    1728
#define KP_2000 2048
#define KP_256  256
#define KP_128  128
#define NP_2000 2048
#define NP_1716 1792
#define NP_256  256
#define NP_128  128

// output layout
#define OFF_EMB1  0ull
#define OFF_BETA  1280000ull
#define OFF_XBAR  1300000ull
#define OFF_PAIRS 18460000ull
#define OFF_LAB   44060000ull

// ---------------- fp32 scratch ----------------
__device__ float g_tra1[NN * DE1];
__device__ float g_tra2[NN * DE2];
__device__ float g_z   [NN * DZ ];
__device__ float g_dec1[NN * DE2];
__device__ float g_dec2[NN * DE1];
__device__ float g_s1  [NN * DE1];
__device__ float g_h1  [NN * DE1];
__device__ float g_s2  [NN * DE2];
__device__ float g_h2  [NN * DE2];
__device__ float g_s3  [NN * DZ ];
__device__ float g_h3  [NN * DZ ];
__device__ float g_emb1[NN * DZ ];
__device__ int   g_rowptr[NN + 1];

// ---------------- bf16 split scratch ----------------
__device__ __nv_bfloat16 g_xh   [(size_t)MP * KP_X];
__device__ __nv_bfloat16 g_xl   [(size_t)MP * KP_X];
__device__ __nv_bfloat16 g_a2kh [(size_t)MP * KP_2000];
__device__ __nv_bfloat16 g_a2kl [(size_t)MP * KP_2000];
__device__ __nv_bfloat16 g_a256h[(size_t)MP * KP_256];
__device__ __nv_bfloat16 g_a256l[(size_t)MP * KP_256];
__device__ __nv_bfloat16 g_a128h[(size_t)MP * KP_128];
__device__ __nv_bfloat16 g_a128l[(size_t)MP * KP_128];
__device__ __nv_bfloat16 g_bth  [(size_t)2048 * 2048];
__device__ __nv_bfloat16 g_btl  [(size_t)2048 * 2048];

// ---------------- small PTX helpers (generic, compute_100-safe) ----------------
__device__ __forceinline__ uint32_t smem_u32(const void* p) {
    uint32_t a;
    asm("{ .reg .u64 t; cvta.to.shared.u64 t, %1; cvt.u32.u64 %0, t; }" : "=r"(a) : "l"(p));
    return a;
}
#define CP_ASYNC16(dst, src) \
    asm volatile("cp.async.cg.shared.global [%0], [%1], 16;" :: "r"(dst), "l"(src) : "memory")
#define CP_COMMIT() asm volatile("cp.async.commit_group;" ::: "memory")

__device__ __forceinline__ void mma_bf16(float* c, const uint32_t* a, uint32_t b0, uint32_t b1) {
    asm volatile(
        "mma.sync.aligned.m16n8k16.row.col.f32.bf16.bf16.f32 "
        "{%0,%1,%2,%3}, {%4,%5,%6,%7}, {%8,%9}, {%0,%1,%2,%3};"
        : "+f"(c[0]), "+f"(c[1]), "+f"(c[2]), "+f"(c[3])
        : "r"(a[0]), "r"(a[1]), "r"(a[2]), "r"(a[3]), "r"(b0), "r"(b1));
}

// ---------------- bf16-split HMMA GEMM ----------------
// C[M,N] = A[M,Kp] @ B[N,Kp]^T, with A,B as (hi,lo) bf16 splits.
// CTA tile 128x128, BK=32, 8 warps (32x64 each). Double-buffered cp.async.
#define SROW    80                   // bytes per smem row (32 bf16 + 8 pad)
#define TILE_B  (128 * SROW)         // 10240 B
#define STAGE_B (4 * TILE_B)         // Ah,Al,Bh,Bl
#define DSMEM_BYTES (2 * STAGE_B)    // 81920 B

template <bool RELU, bool BIAS>
__global__ void __launch_bounds__(256, 1)
hmma_gemm(int Mreal, int Nreal, int Kp, int ldC,
          const __nv_bfloat16* __restrict__ Ah, const __nv_bfloat16* __restrict__ Al,
          const __nv_bfloat16* __restrict__ Bh, const __nv_bfloat16* __restrict__ Bl,
          const float* __restrict__ bias, float* __restrict__ C)
{
    extern __shared__ char dsm[];
    const uint32_t sbase = smem_u32(dsm);

    const int tid  = threadIdx.x;
    const int wid  = tid >> 5;
    const int lane = tid & 31;
    const int Arow0 = blockIdx.y * 128;
    const int Brow0 = blockIdx.x * 128;

    // loader mapping: each thread loads 2x16B from each of the 4 tiles
    const int lrow = tid >> 1;            // 0..127
    const int lseg = (tid & 1) * 2;       // 0 or 2  (16B segments)
    const size_t gA = (size_t)(Arow0 + lrow) * Kp;
    const size_t gB = (size_t)(Brow0 + lrow) * Kp;

    // warp tiling: 4 warps along M, 2 along N
    const int m0 = (wid & 3) * 32;
    const int n0 = (wid >> 2) * 64;
    const int l4 = lane >> 2;             // 0..7
    const int l2 = (lane & 3) * 2;        // 0,2,4,6

    float acc[2][8][4];
#pragma unroll
    for (int mt = 0; mt < 2; mt++)
#pragma unroll
        for (int nt = 0; nt < 8; nt++)
#pragma unroll
            for (int i = 0; i < 4; i++) acc[mt][nt][i] = 0.f;

    const int nk = Kp >> 5;   // chunks of 32

    // ---- stage loader (issues 8 cp.async per thread) ----
    auto load_stage = [&](int s, int k0) {
        const uint32_t st = sbase + s * STAGE_B + lrow * SROW + lseg * 16;
        const size_t goff = (size_t)k0 + lseg * 8;   // elements
#pragma unroll
        for (int seg = 0; seg < 2; seg++) {
            const uint32_t d = st + seg * 16;
            const size_t   g = goff + seg * 8;
            CP_ASYNC16(d,              Ah + gA + g);
            CP_ASYNC16(d + TILE_B,     Al + gA + g);
            CP_ASYNC16(d + 2 * TILE_B, Bh + gB + g);
            CP_ASYNC16(d + 3 * TILE_B, Bl + gB + g);
        }
    };

    load_stage(0, 0);
    CP_COMMIT();

    for (int c0 = 0; c0 < nk; c0++) {
        const int s = c0 & 1;
        if (c0 + 1 < nk) {
            load_stage(s ^ 1, (c0 + 1) << 5);
            CP_COMMIT();
            asm volatile("cp.async.wait_group 1;" ::: "memory");
        } else {
            asm volatile("cp.async.wait_group 0;" ::: "memory");
        }
        __syncthreads();

        const char* sb   = dsm + s * STAGE_B;
        const char* As_h = sb;
        const char* As_l = sb + TILE_B;
        const char* Bs_h = sb + 2 * TILE_B;
        const char* Bs_l = sb + 3 * TILE_B;

#pragma unroll
        for (int kk = 0; kk < 32; kk += 16) {
            const int ca = (kk + l2) * 2;     // byte col offset for A/B frag loads
            uint32_t Afh[2][4], Afl[2][4];
#pragma unroll
            for (int mt = 0; mt < 2; mt++) {
                const int r = m0 + mt * 16 + l4;
                Afh[mt][0] = *(const uint32_t*)(As_h + r * SROW + ca);
                Afh[mt][1] = *(const uint32_t*)(As_h + (r + 8) * SROW + ca);
                Afh[mt][2] = *(const uint32_t*)(As_h + r * SROW + ca + 16);
                Afh[mt][3] = *(const uint32_t*)(As_h + (r + 8) * SROW + ca + 16);
                Afl[mt][0] = *(const uint32_t*)(As_l + r * SROW + ca);
                Afl[mt][1] = *(const uint32_t*)(As_l + (r + 8) * SROW + ca);
                Afl[mt][2] = *(const uint32_t*)(As_l + r * SROW + ca + 16);
                Afl[mt][3] = *(const uint32_t*)(As_l + (r + 8) * SROW + ca + 16);
            }
#pragma unroll
            for (int nt = 0; nt < 8; nt++) {
                const int n = n0 + nt * 8 + l4;
                const uint32_t bh0 = *(const uint32_t*)(Bs_h + n * SROW + ca);
                const uint32_t bh1 = *(const uint32_t*)(Bs_h + n * SROW + ca + 16);
                const uint32_t bl0 = *(const uint32_t*)(Bs_l + n * SROW + ca);
                const uint32_t bl1 = *(const uint32_t*)(Bs_l + n * SROW + ca + 16);
#pragma unroll
                for (int mt = 0; mt < 2; mt++) {
                    mma_bf16(acc[mt][nt], Afh[mt], bh0, bh1);
                    mma_bf16(acc[mt][nt], Afh[mt], bl0, bl1);
                    mma_bf16(acc[mt][nt], Afl[mt], bh0, bh1);
                }
            }
        }
        __syncthreads();
    }

    // ---- epilogue ----
#pragma unroll
    for (int mt = 0; mt < 2; mt++) {
        const int r0 = Arow0 + m0 + mt * 16 + l4;
#pragma unroll
        for (int nt = 0; nt < 8; nt++) {
            const int cc = Brow0 + n0 + nt * 8 + l2;
#pragma unroll
            for (int half = 0; half < 2; half++) {
                const int rr = r0 + half * 8;
                if (rr >= Mreal) continue;
#pragma unroll
                for (int j = 0; j < 2; j++) {
                    const int col = cc + j;
                    if (col >= Nreal) continue;
                    float v = acc[mt][nt][half * 2 + j];
                    if (BIAS) v += bias[col];
                    if (RELU) v = fmaxf(v, 0.f);
                    C[(size_t)rr * ldC + col] = v;
                }
            }
        }
    }
}

// ---------------- conversion: fp32 [M,K] -> bf16 hi/lo [MP,Kp] (optional 0.5*(A+A2)) ----------------
__global__ void split_kernel(const float* __restrict__ A, const float* __restrict__ A2,
                             int M, int K, int Kp,
                             __nv_bfloat16* __restrict__ hi, __nv_bfloat16* __restrict__ lo)
{
    size_t idx = (size_t)blockIdx.x * blockDim.x + threadIdx.x;
    size_t total = (size_t)MP * Kp;
    if (idx >= total) return;
    int r = (int)(idx / Kp), c = (int)(idx % Kp);
    float v = 0.f;
    if (r < M && c < K) {
        size_t s = (size_t)r * K + c;
        v = A2 ? 0.5f * (A[s] + A2[s]) : A[s];
    }
    __nv_bfloat16 h = __float2bfloat16(v);
    hi[idx] = h;
    lo[idx] = __float2bfloat16(v - __bfloat162float(h));
}

// ---------------- W [K,N] fp32 -> Bt [Np,Kp] bf16 hi/lo (transposed) ----------------
__global__ void tsplit_kernel(const float* __restrict__ W, int K, int N, int Kp, int Np,
                              __nv_bfloat16* __restrict__ hi, __nv_bfloat16* __restrict__ lo)
{
    size_t idx = (size_t)blockIdx.x * blockDim.x + threadIdx.x;
    size_t total = (size_t)Np * Kp;
    if (idx >= total) return;
    int n = (int)(idx / Kp), k = (int)(idx % Kp);
    float v = (k < K && n < N) ? W[(size_t)k * N + n] : 0.f;
    __nv_bfloat16 h = __float2bfloat16(v);
    hi[idx] = h;
    lo[idx] = __float2bfloat16(v - __bfloat162float(h));
}

// ---------------- sorted-COO -> row_ptr ----------------
__global__ void build_rowptr_kernel(const int* __restrict__ rows)
{
    int r = blockIdx.x * blockDim.x + threadIdx.x;
    if (r > NN) return;
    int lo = 0, hi = NE;
    while (lo < hi) { int m = (lo + hi) >> 1; if (rows[m] < r) lo = m + 1; else hi = m; }
    g_rowptr[r] = lo;
}

// ---------------- SpMM + relu ----------------
__global__ void spmm_relu_kernel(const int* __restrict__ cols, const float* __restrict__ vals,
                                 const float* __restrict__ sup, int C, float* __restrict__ out)
{
    int r = blockIdx.y;
    int c = blockIdx.x * blockDim.x + threadIdx.x;
    if (c >= C) return;
    float acc = 0.f;
    int e0 = g_rowptr[r], e1 = g_rowptr[r + 1];
    for (int e = e0; e < e1; e++)
        acc += vals[e] * sup[(size_t)cols[e] * C + c];
    out[(size_t)r * C + c] = fmaxf(acc, 0.f);
}

// ---------------- attention fusion ----------------
__global__ void __launch_bounds__(128)
attention_kernel(const float* __restrict__ Wa1, const float* __restrict__ ba1,
                 const float* __restrict__ Wa2, float* __restrict__ out)
{
    int i = blockIdx.x, t = threadIdx.x;
    __shared__ float h3s[DZ], zs[DZ], red0[DZ], red1[DZ];
    __shared__ float b0s, b1s;
    h3s[t] = g_h3[(size_t)i * DZ + t];
    zs[t]  = g_z [(size_t)i * DZ + t];
    __syncthreads();
    float s0 = ba1[t], s1 = ba1[t];
    for (int k = 0; k < DZ; k++) {
        float w = Wa1[k * DZ + t];
        s0 += h3s[k] * w; s1 += zs[k] * w;
    }
    float wa2 = Wa2[t];
    red0[t] = tanhf(s0) * wa2;
    red1[t] = tanhf(s1) * wa2;
    __syncthreads();
    for (int s = 64; s > 0; s >>= 1) {
        if (t < s) { red0[t] += red0[t + s]; red1[t] += red1[t + s]; }
        __syncthreads();
    }
    if (t == 0) {
        float w0 = red0[0], w1 = red1[0];
        float m = fmaxf(w0, w1);
        float e0 = expf(w0 - m), e1 = expf(w1 - m);
        float inv = 1.f / (e0 + e1);
        b0s = e0 * inv; b1s = e1 * inv;
        out[OFF_BETA + (size_t)i * 2 + 0] = b0s;
        out[OFF_BETA + (size_t)i * 2 + 1] = b1s;
    }
    __syncthreads();
    float e = b0s * h3s[t] + b1s * zs[t];
    g_emb1[(size_t)i * DZ + t] = e;
    out[OFF_EMB1 + (size_t)i * DZ + t] = e;
}

__global__ void pairs_kernel(const int* __restrict__ pair_idx, float* __restrict__ out)
{
    long long idx = (long long)blockIdx.x * blockDim.x + threadIdx.x;
    if (idx >= (long long)NP * DZ) return;
    int p = (int)(idx >> 7), c = (int)(idx & 127);
    int a = pair_idx[2 * p], b = pair_idx[2 * p + 1];
    out[OFF_PAIRS + idx] = 0.5f * (g_emb1[(size_t)a * DZ + c] + g_emb1[(size_t)b * DZ + c]);
}

__global__ void labels_kernel(const int* __restrict__ labels, float* __restrict__ out)
{
    int p = blockIdx.x * blockDim.x + threadIdx.x;
    if (p >= NP) return;
    out[OFF_LAB + p] = (float)labels[p];
}

// ---------------- host helpers ----------------
static inline unsigned nblk(size_t n) { return (unsigned)((n + 255) / 256); }

template <bool RELU, bool BIAS>
static void launch_gemm(int Mreal, int Nreal, int Kp, int Np, int ldC,
                        const __nv_bfloat16* Ah, const __nv_bfloat16* Al,
                        const __nv_bfloat16* Bh, const __nv_bfloat16* Bl,
                        const float* bias, float* C)
{
    static bool attr_done = false;
    cudaFuncSetAttribute(hmma_gemm<RELU, BIAS>,
                         cudaFuncAttributeMaxDynamicSharedMemorySize, DSMEM_BYTES);
    (void)attr_done;
    dim3 grid(Np / 128, MP / 128);
    hmma_gemm<RELU, BIAS><<<grid, 256, DSMEM_BYTES>>>(Mreal, Nreal, Kp, ldC, Ah, Al, Bh, Bl, bias, C);
}

extern "C" void kernel_launch(void* const* d_in, const int* in_sizes, int n_in,
                              void* d_out, int out_size)
{
    const float* x        = (const float*)d_in[0];
    const int*   adj_rows = (const int*)  d_in[1];
    const int*   adj_cols = (const int*)  d_in[2];
    const float* adj_vals = (const float*)d_in[3];
    const int*   pair_idx = (const int*)  d_in[4];
    const int*   labels   = (const int*)  d_in[5];
    const float* W_enc1 = (const float*)d_in[6];
    const float* b_enc1 = (const float*)d_in[7];
    const float* W_enc2 = (const float*)d_in[8];
    const float* b_enc2 = (const float*)d_in[9];
    const float* W_z    = (const float*)d_in[10];
    const float* b_z    = (const float*)d_in[11];
    const float* W_dec1 = (const float*)d_in[12];
    const float* b_dec1 = (const float*)d_in[13];
    const float* W_dec2 = (const float*)d_in[14];
    const float* b_dec2 = (const float*)d_in[15];
    const float* W_xbar = (const float*)d_in[16];
    const float* b_xbar = (const float*)d_in[17];
    const float* W_g1   = (const float*)d_in[18];
    const float* W_g2   = (const float*)d_in[19];
    const float* W_g3   = (const float*)d_in[20];
    const float* W_a1   = (const float*)d_in[21];
    const float* b_a1   = (const float*)d_in[22];
    const float* W_a2   = (const float*)d_in[23];
    float* out = (float*)d_out;

    float *tra1, *tra2, *z, *dec1, *dec2, *s1, *h1, *s2, *h2, *s3, *h3;
    __nv_bfloat16 *xh, *xl, *a2kh, *a2kl, *a256h, *a256l, *a128h, *a128l, *bth, *btl;
    cudaGetSymbolAddress((void**)&tra1, g_tra1);
    cudaGetSymbolAddress((void**)&tra2, g_tra2);
    cudaGetSymbolAddress((void**)&z,    g_z);
    cudaGetSymbolAddress((void**)&dec1, g_dec1);
    cudaGetSymbolAddress((void**)&dec2, g_dec2);
    cudaGetSymbolAddress((void**)&s1,   g_s1);
    cudaGetSymbolAddress((void**)&h1,   g_h1);
    cudaGetSymbolAddress((void**)&s2,   g_s2);
    cudaGetSymbolAddress((void**)&h2,   g_h2);
    cudaGetSymbolAddress((void**)&s3,   g_s3);
    cudaGetSymbolAddress((void**)&h3,   g_h3);
    cudaGetSymbolAddress((void**)&xh,    g_xh);
    cudaGetSymbolAddress((void**)&xl,    g_xl);
    cudaGetSymbolAddress((void**)&a2kh,  g_a2kh);
    cudaGetSymbolAddress((void**)&a2kl,  g_a2kl);
    cudaGetSymbolAddress((void**)&a256h, g_a256h);
    cudaGetSymbolAddress((void**)&a256l, g_a256l);
    cudaGetSymbolAddress((void**)&a128h, g_a128h);
    cudaGetSymbolAddress((void**)&a128l, g_a128l);
    cudaGetSymbolAddress((void**)&bth,   g_bth);
    cudaGetSymbolAddress((void**)&btl,   g_btl);

    build_rowptr_kernel<<<(NN + 256) / 256, 256>>>(adj_rows);

    // ---- split x (shared by enc1 and g1) ----
    split_kernel<<<nblk((size_t)MP * KP_X), 256>>>(x, nullptr, NN, DIN, KP_X, xh, xl);

    // enc1: tra1 = relu(x @ W_enc1 + b)
    tsplit_kernel<<<nblk((size_t)NP_2000 * KP_X), 256>>>(W_enc1, DIN, DE1, KP_X, NP_2000, bth, btl);
    launch_gemm<true, true>(NN, DE1, KP_X, NP_2000, DE1, xh, xl, bth, btl, b_enc1, tra1);

    // g1: s1 = x @ W_g1 (reuses xh/xl before they are overwritten by later splits)
    tsplit_kernel<<<nblk((size_t)NP_2000 * KP_X), 256>>>(W_g1, DIN, DE1, KP_X, NP_2000, bth, btl);
    launch_gemm<false, false>(NN, DE1, KP_X, NP_2000, DE1, xh, xl, bth, btl, nullptr, s1);
    spmm_relu_kernel<<<dim3((DE1 + 255) / 256, NN), 256>>>(adj_cols, adj_vals, s1, DE1, h1);

    // enc2: tra2 = relu(tra1 @ W_enc2 + b)
    split_kernel<<<nblk((size_t)MP * KP_2000), 256>>>(tra1, nullptr, NN, DE1, KP_2000, a2kh, a2kl);
    tsplit_kernel<<<nblk((size_t)NP_256 * KP_2000), 256>>>(W_enc2, DE1, DE2, KP_2000, NP_256, bth, btl);
    launch_gemm<true, true>(NN, DE2, KP_2000, NP_256, DE2, a2kh, a2kl, bth, btl, b_enc2, tra2);

    // z = tra2 @ W_z + b
    split_kernel<<<nblk((size_t)MP * KP_256), 256>>>(tra2, nullptr, NN, DE2, KP_256, a256h, a256l);
    tsplit_kernel<<<nblk((size_t)NP_128 * KP_256), 256>>>(W_z, DE2, DZ, KP_256, NP_128, bth, btl);
    launch_gemm<false, true>(NN, DZ, KP_256, NP_128, DZ, a256h, a256l, bth, btl, b_z, z);

    // dec1 = relu(z @ W_dec1 + b)
    split_kernel<<<nblk((size_t)MP * KP_128), 256>>>(z, nullptr, NN, DZ, KP_128, a128h, a128l);
    tsplit_kernel<<<nblk((size_t)NP_256 * KP_128), 256>>>(W_dec1, DZ, DE2, KP_128, NP_256, bth, btl);
    launch_gemm<true, true>(NN, DE2, KP_128, NP_256, DE2, a128h, a128l, bth, btl, b_dec1, dec1);

    // dec2 = relu(dec1 @ W_dec2 + b)
    split_kernel<<<nblk((size_t)MP * KP_256), 256>>>(dec1, nullptr, NN, DE2, KP_256, a256h, a256l);
    tsplit_kernel<<<nblk((size_t)NP_2000 * KP_256), 256>>>(W_dec2, DE2, DE1, KP_256, NP_2000, bth, btl);
    launch_gemm<true, true>(NN, DE1, KP_256, NP_2000, DE1, a256h, a256l, bth, btl, b_dec2, dec2);

    // x_bar = dec2 @ W_xbar + b  (direct to output)
    split_kernel<<<nblk((size_t)MP * KP_2000), 256>>>(dec2, nullptr, NN, DE1, KP_2000, a2kh, a2kl);
    tsplit_kernel<<<nblk((size_t)NP_1716 * KP_2000), 256>>>(W_xbar, DE1, DIN, KP_2000, NP_1716, bth, btl);
    launch_gemm<false, true>(NN, DIN, KP_2000, NP_1716, DIN, a2kh, a2kl, bth, btl, b_xbar, out + OFF_XBAR);

    // g2: h2 = relu(spmm((0.5 h1 + 0.5 tra1) @ W_g2))
    split_kernel<<<nblk((size_t)MP * KP_2000), 256>>>(h1, tra1, NN, DE1, KP_2000, a2kh, a2kl);
    tsplit_kernel<<<nblk((size_t)NP_256 * KP_2000), 256>>>(W_g2, DE1, DE2, KP_2000, NP_256, bth, btl);
    launch_gemm<false, false>(NN, DE2, KP_2000, NP_256, DE2, a2kh, a2kl, bth, btl, nullptr, s2);
    spmm_relu_kernel<<<dim3((DE2 + 255) / 256, NN), 256>>>(adj_cols, adj_vals, s2, DE2, h2);

    // g3: h3 = relu(spmm((0.5 h2 + 0.5 tra2) @ W_g3))
    split_kernel<<<nblk((size_t)MP * KP_256), 256>>>(h2, tra2, NN, DE2, KP_256, a256h, a256l);
    tsplit_kernel<<<nblk((size_t)NP_128 * KP_256), 256>>>(W_g3, DE2, DZ, KP_256, NP_128, bth, btl);
    launch_gemm<false, false>(NN, DZ, KP_256, NP_128, DZ, a256h, a256l, bth, btl, nullptr, s3);
    spmm_relu_kernel<<<dim3((DZ + 255) / 256, NN), 256>>>(adj_cols, adj_vals, s3, DZ, h3);

    // ---- attention fusion + outputs ----
    attention_kernel<<<NN, 128>>>(W_a1, b_a1, W_a2, out);
    pairs_kernel<<<nblk((size_t)NP * DZ), 256>>>(pair_idx, out);
    labels_kernel<<<(NP + 255) / 256, 256>>>(labels, out);
}

// round 5
// speedup vs baseline: 2.5986x; 1.1858x over previous
#include <cuda_runtime.h>
#include <cuda_bf16.h>
#include <cstdint>

// ---------------- problem constants ----------------
#define NN   10000
#define DIN  1716
#define DE1  2000
#define DE2  256
#define DZ   128
#define NE   100000
#define NP   200000
#define MP   10112      // NN padded to 128

#define KP_X    1728
#define KP_2000 2048
#define KP_256  256
#define KP_128  128
#define NP_2000 2048
#define NP_1716 1792
#define NP_256  256
#define NP_128  128

// output layout
#define OFF_EMB1  0ull
#define OFF_BETA  1280000ull
#define OFF_XBAR  1300000ull
#define OFF_PAIRS 18460000ull
#define OFF_LAB   44060000ull

// ---------------- fp32 scratch ----------------
__device__ float g_tra1[NN * DE1];
__device__ float g_tra2[NN * DE2];
__device__ float g_z   [NN * DZ ];
__device__ float g_s1  [NN * DE1];
__device__ float g_s2  [NN * DE2];
__device__ float g_s3  [NN * DZ ];
__device__ float g_h3  [NN * DZ ];
__device__ float g_emb1[NN * DZ ];
__device__ int   g_rowptr[NN + 1];

// ---------------- bf16 split scratch ----------------
__device__ __nv_bfloat16 g_xh [(size_t)MP * KP_X];
__device__ __nv_bfloat16 g_xl [(size_t)MP * KP_X];
__device__ __nv_bfloat16 g_t1h[(size_t)MP * KP_2000];   // tra1 split
__device__ __nv_bfloat16 g_t1l[(size_t)MP * KP_2000];
__device__ __nv_bfloat16 g_m1h[(size_t)MP * KP_2000];   // mix(h1,tra1) split
__device__ __nv_bfloat16 g_m1l[(size_t)MP * KP_2000];
__device__ __nv_bfloat16 g_t2h[(size_t)MP * KP_256];    // tra2 split
__device__ __nv_bfloat16 g_t2l[(size_t)MP * KP_256];
__device__ __nv_bfloat16 g_m2h[(size_t)MP * KP_256];    // mix(h2,tra2) split
__device__ __nv_bfloat16 g_m2l[(size_t)MP * KP_256];
__device__ __nv_bfloat16 g_zsh[(size_t)MP * KP_128];    // z split
__device__ __nv_bfloat16 g_zsl[(size_t)MP * KP_128];
__device__ __nv_bfloat16 g_d1h[(size_t)MP * KP_256];    // dec1 split
__device__ __nv_bfloat16 g_d1l[(size_t)MP * KP_256];
__device__ __nv_bfloat16 g_d2h[(size_t)MP * KP_2000];   // dec2 split
__device__ __nv_bfloat16 g_d2l[(size_t)MP * KP_2000];
__device__ __nv_bfloat16 g_bth[(size_t)2048 * 2048];    // weight^T split
__device__ __nv_bfloat16 g_btl[(size_t)2048 * 2048];

// ---------------- PTX helpers (compute_100-generic) ----------------
__device__ __forceinline__ uint32_t smem_u32(const void* p) {
    uint32_t a;
    asm("{ .reg .u64 t; cvta.to.shared.u64 t, %1; cvt.u32.u64 %0, t; }" : "=r"(a) : "l"(p));
    return a;
}
#define CP_ASYNC16(dst, src) \
    asm volatile("cp.async.cg.shared.global [%0], [%1], 16;" :: "r"(dst), "l"(src) : "memory")
#define CP_COMMIT() asm volatile("cp.async.commit_group;" ::: "memory")

__device__ __forceinline__ void mma_bf16(float* c, const uint32_t* a, uint32_t b0, uint32_t b1) {
    asm volatile(
        "mma.sync.aligned.m16n8k16.row.col.f32.bf16.bf16.f32 "
        "{%0,%1,%2,%3}, {%4,%5,%6,%7}, {%8,%9}, {%0,%1,%2,%3};"
        : "+f"(c[0]), "+f"(c[1]), "+f"(c[2]), "+f"(c[3])
        : "r"(a[0]), "r"(a[1]), "r"(a[2]), "r"(a[3]), "r"(b0), "r"(b1));
}

// ---------------- bf16-split HMMA GEMM with fused split epilogue ----------------
#define SROW    80
#define TILE_B  (128 * SROW)
#define STAGE_B (4 * TILE_B)
#define DSMEM_BYTES (2 * STAGE_B)    // 81920 B

template <bool RELU, bool BIAS>
__global__ void __launch_bounds__(256, 2)
hmma_gemm(int Mreal, int Nreal, int Kp, int ldC, int Npad,
          const __nv_bfloat16* __restrict__ Ah, const __nv_bfloat16* __restrict__ Al,
          const __nv_bfloat16* __restrict__ Bh, const __nv_bfloat16* __restrict__ Bl,
          const float* __restrict__ bias, float* __restrict__ Cf,
          __nv_bfloat16* __restrict__ Sh, __nv_bfloat16* __restrict__ Sl)
{
    extern __shared__ char dsm[];
    const uint32_t sbase = smem_u32(dsm);

    const int tid  = threadIdx.x;
    const int wid  = tid >> 5;
    const int lane = tid & 31;
    const int Arow0 = blockIdx.y * 128;
    const int Brow0 = blockIdx.x * 128;

    const int lrow = tid >> 1;
    const int lseg = (tid & 1) * 2;
    const size_t gA = (size_t)(Arow0 + lrow) * Kp;
    const size_t gB = (size_t)(Brow0 + lrow) * Kp;

    const int m0 = (wid & 3) * 32;
    const int n0 = (wid >> 2) * 64;
    const int l4 = lane >> 2;
    const int l2 = (lane & 3) * 2;

    float acc[2][8][4];
#pragma unroll
    for (int mt = 0; mt < 2; mt++)
#pragma unroll
        for (int nt = 0; nt < 8; nt++)
#pragma unroll
            for (int i = 0; i < 4; i++) acc[mt][nt][i] = 0.f;

    const int nk = Kp >> 5;

    auto load_stage = [&](int s, int k0) {
        const uint32_t st = sbase + s * STAGE_B + lrow * SROW + lseg * 16;
        const size_t goff = (size_t)k0 + lseg * 8;
#pragma unroll
        for (int seg = 0; seg < 2; seg++) {
            const uint32_t d = st + seg * 16;
            const size_t   g = goff + seg * 8;
            CP_ASYNC16(d,              Ah + gA + g);
            CP_ASYNC16(d + TILE_B,     Al + gA + g);
            CP_ASYNC16(d + 2 * TILE_B, Bh + gB + g);
            CP_ASYNC16(d + 3 * TILE_B, Bl + gB + g);
        }
    };

    load_stage(0, 0);
    CP_COMMIT();

    for (int c0 = 0; c0 < nk; c0++) {
        const int s = c0 & 1;
        if (c0 + 1 < nk) {
            load_stage(s ^ 1, (c0 + 1) << 5);
            CP_COMMIT();
            asm volatile("cp.async.wait_group 1;" ::: "memory");
        } else {
            asm volatile("cp.async.wait_group 0;" ::: "memory");
        }
        __syncthreads();

        const char* sb   = dsm + s * STAGE_B;
        const char* As_h = sb;
        const char* As_l = sb + TILE_B;
        const char* Bs_h = sb + 2 * TILE_B;
        const char* Bs_l = sb + 3 * TILE_B;

#pragma unroll
        for (int kk = 0; kk < 32; kk += 16) {
            const int ca = (kk + l2) * 2;
            uint32_t Afh[2][4], Afl[2][4];
#pragma unroll
            for (int mt = 0; mt < 2; mt++) {
                const int r = m0 + mt * 16 + l4;
                Afh[mt][0] = *(const uint32_t*)(As_h + r * SROW + ca);
                Afh[mt][1] = *(const uint32_t*)(As_h + (r + 8) * SROW + ca);
                Afh[mt][2] = *(const uint32_t*)(As_h + r * SROW + ca + 16);
                Afh[mt][3] = *(const uint32_t*)(As_h + (r + 8) * SROW + ca + 16);
                Afl[mt][0] = *(const uint32_t*)(As_l + r * SROW + ca);
                Afl[mt][1] = *(const uint32_t*)(As_l + (r + 8) * SROW + ca);
                Afl[mt][2] = *(const uint32_t*)(As_l + r * SROW + ca + 16);
                Afl[mt][3] = *(const uint32_t*)(As_l + (r + 8) * SROW + ca + 16);
            }
#pragma unroll
            for (int nt = 0; nt < 8; nt++) {
                const int n = n0 + nt * 8 + l4;
                const uint32_t bh0 = *(const uint32_t*)(Bs_h + n * SROW + ca);
                const uint32_t bh1 = *(const uint32_t*)(Bs_h + n * SROW + ca + 16);
                const uint32_t bl0 = *(const uint32_t*)(Bs_l + n * SROW + ca);
                const uint32_t bl1 = *(const uint32_t*)(Bs_l + n * SROW + ca + 16);
#pragma unroll
                for (int mt = 0; mt < 2; mt++) {
                    mma_bf16(acc[mt][nt], Afh[mt], bh0, bh1);
                    mma_bf16(acc[mt][nt], Afh[mt], bl0, bl1);
                    mma_bf16(acc[mt][nt], Afl[mt], bh0, bh1);
                }
            }
        }
        __syncthreads();
    }

    // ---- epilogue: fp32 C (valid region) + optional bf16 hi/lo split (padded) ----
#pragma unroll
    for (int mt = 0; mt < 2; mt++) {
#pragma unroll
        for (int half = 0; half < 2; half++) {
            const int rr = Arow0 + m0 + mt * 16 + l4 + half * 8;
            const bool rok = rr < Mreal;
#pragma unroll
            for (int nt = 0; nt < 8; nt++) {
#pragma unroll
                for (int j = 0; j < 2; j++) {
                    const int col = Brow0 + n0 + nt * 8 + l2 + j;
                    float v = 0.f;
                    if (rok && col < Nreal) {
                        v = acc[mt][nt][half * 2 + j];
                        if (BIAS) v += bias[col];
                        if (RELU) v = fmaxf(v, 0.f);
                        if (Cf) Cf[(size_t)rr * ldC + col] = v;
                    }
                    if (Sh) {
                        __nv_bfloat16 h = __float2bfloat16(v);
                        const size_t so = (size_t)rr * Npad + col;
                        Sh[so] = h;
                        Sl[so] = __float2bfloat16(v - __bfloat162float(h));
                    }
                }
            }
        }
    }
}

// ---------------- x split ----------------
__global__ void split_kernel(const float* __restrict__ A, int M, int K, int Kp,
                             __nv_bfloat16* __restrict__ hi, __nv_bfloat16* __restrict__ lo)
{
    size_t idx = (size_t)blockIdx.x * blockDim.x + threadIdx.x;
    size_t total = (size_t)MP * Kp;
    if (idx >= total) return;
    int r = (int)(idx / Kp), c = (int)(idx % Kp);
    float v = (r < M && c < K) ? A[(size_t)r * K + c] : 0.f;
    __nv_bfloat16 h = __float2bfloat16(v);
    hi[idx] = h;
    lo[idx] = __float2bfloat16(v - __bfloat162float(h));
}

// ---------------- W [K,N] fp32 -> Bt [Np,Kp] bf16 hi/lo ----------------
__global__ void tsplit_kernel(const float* __restrict__ W, int K, int N, int Kp, int Np,
                              __nv_bfloat16* __restrict__ hi, __nv_bfloat16* __restrict__ lo)
{
    size_t idx = (size_t)blockIdx.x * blockDim.x + threadIdx.x;
    size_t total = (size_t)Np * Kp;
    if (idx >= total) return;
    int n = (int)(idx / Kp), k = (int)(idx % Kp);
    float v = (k < K && n < N) ? W[(size_t)k * N + n] : 0.f;
    __nv_bfloat16 h = __float2bfloat16(v);
    hi[idx] = h;
    lo[idx] = __float2bfloat16(v - __bfloat162float(h));
}

// ---------------- sorted-COO -> row_ptr ----------------
__global__ void build_rowptr_kernel(const int* __restrict__ rows)
{
    int r = blockIdx.x * blockDim.x + threadIdx.x;
    if (r > NN) return;
    int lo = 0, hi = NE;
    while (lo < hi) { int m = (lo + hi) >> 1; if (rows[m] < r) lo = m + 1; else hi = m; }
    g_rowptr[r] = lo;
}

// ---------------- SpMM + relu + mix + split (layers 1,2) ----------------
__global__ void spmm_mix_split_kernel(const int* __restrict__ cols, const float* __restrict__ vals,
                                      const float* __restrict__ sup, const float* __restrict__ tra,
                                      int Creal, int Cpad,
                                      __nv_bfloat16* __restrict__ Sh, __nv_bfloat16* __restrict__ Sl)
{
    int r = blockIdx.y;
    int c = blockIdx.x * blockDim.x + threadIdx.x;
    if (c >= Cpad) return;
    float v = 0.f;
    if (r < NN && c < Creal) {
        float acc = 0.f;
        int e0 = g_rowptr[r], e1 = g_rowptr[r + 1];
        for (int e = e0; e < e1; e++)
            acc += vals[e] * sup[(size_t)cols[e] * Creal + c];
        v = 0.5f * (fmaxf(acc, 0.f) + tra[(size_t)r * Creal + c]);
    }
    __nv_bfloat16 h = __float2bfloat16(v);
    const size_t so = (size_t)r * Cpad + c;
    Sh[so] = h;
    Sl[so] = __float2bfloat16(v - __bfloat162float(h));
}

// ---------------- SpMM + relu (layer 3, fp32 out) ----------------
__global__ void spmm_relu_kernel(const int* __restrict__ cols, const float* __restrict__ vals,
                                 const float* __restrict__ sup, int C, float* __restrict__ out)
{
    int r = blockIdx.y;
    int c = blockIdx.x * blockDim.x + threadIdx.x;
    if (c >= C) return;
    float acc = 0.f;
    int e0 = g_rowptr[r], e1 = g_rowptr[r + 1];
    for (int e = e0; e < e1; e++)
        acc += vals[e] * sup[(size_t)cols[e] * C + c];
    out[(size_t)r * C + c] = fmaxf(acc, 0.f);
}

// ---------------- attention fusion ----------------
__global__ void __launch_bounds__(128)
attention_kernel(const float* __restrict__ Wa1, const float* __restrict__ ba1,
                 const float* __restrict__ Wa2, float* __restrict__ out)
{
    int i = blockIdx.x, t = threadIdx.x;
    __shared__ float h3s[DZ], zs[DZ], red0[DZ], red1[DZ];
    __shared__ float b0s, b1s;
    h3s[t] = g_h3[(size_t)i * DZ + t];
    zs[t]  = g_z [(size_t)i * DZ + t];
    __syncthreads();
    float s0 = ba1[t], s1 = ba1[t];
    for (int k = 0; k < DZ; k++) {
        float w = Wa1[k * DZ + t];
        s0 += h3s[k] * w; s1 += zs[k] * w;
    }
    float wa2 = Wa2[t];
    red0[t] = tanhf(s0) * wa2;
    red1[t] = tanhf(s1) * wa2;
    __syncthreads();
    for (int s = 64; s > 0; s >>= 1) {
        if (t < s) { red0[t] += red0[t + s]; red1[t] += red1[t + s]; }
        __syncthreads();
    }
    if (t == 0) {
        float w0 = red0[0], w1 = red1[0];
        float m = fmaxf(w0, w1);
        float e0 = expf(w0 - m), e1 = expf(w1 - m);
        float inv = 1.f / (e0 + e1);
        b0s = e0 * inv; b1s = e1 * inv;
        out[OFF_BETA + (size_t)i * 2 + 0] = b0s;
        out[OFF_BETA + (size_t)i * 2 + 1] = b1s;
    }
    __syncthreads();
    float e = b0s * h3s[t] + b1s * zs[t];
    g_emb1[(size_t)i * DZ + t] = e;
    out[OFF_EMB1 + (size_t)i * DZ + t] = e;
}

__global__ void pairs_kernel(const int* __restrict__ pair_idx, float* __restrict__ out)
{
    long long idx = (long long)blockIdx.x * blockDim.x + threadIdx.x;
    if (idx >= (long long)NP * DZ) return;
    int p = (int)(idx >> 7), c = (int)(idx & 127);
    int a = pair_idx[2 * p], b = pair_idx[2 * p + 1];
    out[OFF_PAIRS + idx] = 0.5f * (g_emb1[(size_t)a * DZ + c] + g_emb1[(size_t)b * DZ + c]);
}

__global__ void labels_kernel(const int* __restrict__ labels, float* __restrict__ out)
{
    int p = blockIdx.x * blockDim.x + threadIdx.x;
    if (p >= NP) return;
    out[OFF_LAB + p] = (float)labels[p];
}

// ---------------- host helpers ----------------
static inline unsigned nblk(size_t n) { return (unsigned)((n + 255) / 256); }

template <bool RELU, bool BIAS>
static void launch_gemm(int Mreal, int Nreal, int Kp, int Npad, int ldC,
                        const __nv_bfloat16* Ah, const __nv_bfloat16* Al,
                        const __nv_bfloat16* Bh, const __nv_bfloat16* Bl,
                        const float* bias, float* Cf,
                        __nv_bfloat16* Sh, __nv_bfloat16* Sl)
{
    cudaFuncSetAttribute(hmma_gemm<RELU, BIAS>,
                         cudaFuncAttributeMaxDynamicSharedMemorySize, DSMEM_BYTES);
    dim3 grid(Npad / 128, MP / 128);
    hmma_gemm<RELU, BIAS><<<grid, 256, DSMEM_BYTES>>>(Mreal, Nreal, Kp, ldC, Npad,
                                                      Ah, Al, Bh, Bl, bias, Cf, Sh, Sl);
}

extern "C" void kernel_launch(void* const* d_in, const int* in_sizes, int n_in,
                              void* d_out, int out_size)
{
    const float* x        = (const float*)d_in[0];
    const int*   adj_rows = (const int*)  d_in[1];
    const int*   adj_cols = (const int*)  d_in[2];
    const float* adj_vals = (const float*)d_in[3];
    const int*   pair_idx = (const int*)  d_in[4];
    const int*   labels   = (const int*)  d_in[5];
    const float* W_enc1 = (const float*)d_in[6];
    const float* b_enc1 = (const float*)d_in[7];
    const float* W_enc2 = (const float*)d_in[8];
    const float* b_enc2 = (const float*)d_in[9];
    const float* W_z    = (const float*)d_in[10];
    const float* b_z    = (const float*)d_in[11];
    const float* W_dec1 = (const float*)d_in[12];
    const float* b_dec1 = (const float*)d_in[13];
    const float* W_dec2 = (const float*)d_in[14];
    const float* b_dec2 = (const float*)d_in[15];
    const float* W_xbar = (const float*)d_in[16];
    const float* b_xbar = (const float*)d_in[17];
    const float* W_g1   = (const float*)d_in[18];
    const float* W_g2   = (const float*)d_in[19];
    const float* W_g3   = (const float*)d_in[20];
    const float* W_a1   = (const float*)d_in[21];
    const float* b_a1   = (const float*)d_in[22];
    const float* W_a2   = (const float*)d_in[23];
    float* out = (float*)d_out;

    float *tra1, *tra2, *z, *s1, *s2, *s3, *h3;
    __nv_bfloat16 *xh, *xl, *t1h, *t1l, *m1h, *m1l, *t2h, *t2l, *m2h, *m2l;
    __nv_bfloat16 *zsh, *zsl, *d1h, *d1l, *d2h, *d2l, *bth, *btl;
    cudaGetSymbolAddress((void**)&tra1, g_tra1);
    cudaGetSymbolAddress((void**)&tra2, g_tra2);
    cudaGetSymbolAddress((void**)&z,    g_z);
    cudaGetSymbolAddress((void**)&s1,   g_s1);
    cudaGetSymbolAddress((void**)&s2,   g_s2);
    cudaGetSymbolAddress((void**)&s3,   g_s3);
    cudaGetSymbolAddress((void**)&h3,   g_h3);
    cudaGetSymbolAddress((void**)&xh,  g_xh);
    cudaGetSymbolAddress((void**)&xl,  g_xl);
    cudaGetSymbolAddress((void**)&t1h, g_t1h);
    cudaGetSymbolAddress((void**)&t1l, g_t1l);
    cudaGetSymbolAddress((void**)&m1h, g_m1h);
    cudaGetSymbolAddress((void**)&m1l, g_m1l);
    cudaGetSymbolAddress((void**)&t2h, g_t2h);
    cudaGetSymbolAddress((void**)&t2l, g_t2l);
    cudaGetSymbolAddress((void**)&m2h, g_m2h);
    cudaGetSymbolAddress((void**)&m2l, g_m2l);
    cudaGetSymbolAddress((void**)&zsh, g_zsh);
    cudaGetSymbolAddress((void**)&zsl, g_zsl);
    cudaGetSymbolAddress((void**)&d1h, g_d1h);
    cudaGetSymbolAddress((void**)&d1l, g_d1l);
    cudaGetSymbolAddress((void**)&d2h, g_d2h);
    cudaGetSymbolAddress((void**)&d2l, g_d2l);
    cudaGetSymbolAddress((void**)&bth, g_bth);
    cudaGetSymbolAddress((void**)&btl, g_btl);

    build_rowptr_kernel<<<(NN + 256) / 256, 256>>>(adj_rows);

    // x split (shared by enc1 and g1)
    split_kernel<<<nblk((size_t)MP * KP_X), 256>>>(x, NN, DIN, KP_X, xh, xl);

    // enc1: tra1 = relu(x @ W_enc1 + b); epilogue also emits tra1 split -> t1
    tsplit_kernel<<<nblk((size_t)NP_2000 * KP_X), 256>>>(W_enc1, DIN, DE1, KP_X, NP_2000, bth, btl);
    launch_gemm<true, true>(NN, DE1, KP_X, NP_2000, DE1, xh, xl, bth, btl, b_enc1, tra1, t1h, t1l);

    // g1: s1 = x @ W_g1
    tsplit_kernel<<<nblk((size_t)NP_2000 * KP_X), 256>>>(W_g1, DIN, DE1, KP_X, NP_2000, bth, btl);
    launch_gemm<false, false>(NN, DE1, KP_X, NP_2000, DE1, xh, xl, bth, btl, nullptr, s1, nullptr, nullptr);

    // spmm1 -> mix(h1,tra1) split -> m1
    spmm_mix_split_kernel<<<dim3((KP_2000 + 255) / 256, MP), 256>>>(adj_cols, adj_vals, s1, tra1, DE1, KP_2000, m1h, m1l);

    // enc2: tra2 = relu(tra1 @ W_enc2 + b); epilogue split -> t2
    tsplit_kernel<<<nblk((size_t)NP_256 * KP_2000), 256>>>(W_enc2, DE1, DE2, KP_2000, NP_256, bth, btl);
    launch_gemm<true, true>(NN, DE2, KP_2000, NP_256, DE2, t1h, t1l, bth, btl, b_enc2, tra2, t2h, t2l);

    // z = tra2 @ W_z + b; epilogue split -> zs
    tsplit_kernel<<<nblk((size_t)NP_128 * KP_256), 256>>>(W_z, DE2, DZ, KP_256, NP_128, bth, btl);
    launch_gemm<false, true>(NN, DZ, KP_256, NP_128, DZ, t2h, t2l, bth, btl, b_z, z, zsh, zsl);

    // dec1 = relu(z @ W_dec1 + b); split only -> d1
    tsplit_kernel<<<nblk((size_t)NP_256 * KP_128), 256>>>(W_dec1, DZ, DE2, KP_128, NP_256, bth, btl);
    launch_gemm<true, true>(NN, DE2, KP_128, NP_256, DE2, zsh, zsl, bth, btl, b_dec1, nullptr, d1h, d1l);

    // dec2 = relu(dec1 @ W_dec2 + b); split only -> d2
    tsplit_kernel<<<nblk((size_t)NP_2000 * KP_256), 256>>>(W_dec2, DE2, DE1, KP_256, NP_2000, bth, btl);
    launch_gemm<true, true>(NN, DE1, KP_256, NP_2000, DE1, d1h, d1l, bth, btl, b_dec2, nullptr, d2h, d2l);

    // x_bar = dec2 @ W_xbar + b  (fp32 direct to output)
    tsplit_kernel<<<nblk((size_t)NP_1716 * KP_2000), 256>>>(W_xbar, DE1, DIN, KP_2000, NP_1716, bth, btl);
    launch_gemm<false, true>(NN, DIN, KP_2000, NP_1716, DIN, d2h, d2l, bth, btl, b_xbar, out + OFF_XBAR, nullptr, nullptr);

    // g2: s2 = mix1 @ W_g2
    tsplit_kernel<<<nblk((size_t)NP_256 * KP_2000), 256>>>(W_g2, DE1, DE2, KP_2000, NP_256, bth, btl);
    launch_gemm<false, false>(NN, DE2, KP_2000, NP_256, DE2, m1h, m1l, bth, btl, nullptr, s2, nullptr, nullptr);

    // spmm2 -> mix(h2,tra2) split -> m2
    spmm_mix_split_kernel<<<dim3((KP_256 + 255) / 256, MP), 256>>>(adj_cols, adj_vals, s2, tra2, DE2, KP_256, m2h, m2l);

    // g3: s3 = mix2 @ W_g3
    tsplit_kernel<<<nblk((size_t)NP_128 * KP_256), 256>>>(W_g3, DE2, DZ, KP_256, NP_128, bth, btl);
    launch_gemm<false, false>(NN, DZ, KP_256, NP_128, DZ, m2h, m2l, bth, btl, nullptr, s3, nullptr, nullptr);

    // spmm3 -> h3 fp32
    spmm_relu_kernel<<<dim3((DZ + 255) / 256, NN), 256>>>(adj_cols, adj_vals, s3, DZ, h3);

    // attention fusion + outputs
    attention_kernel<<<NN, 128>>>(W_a1, b_a1, W_a2, out);
    pairs_kernel<<<nblk((size_t)NP * DZ), 256>>>(pair_idx, out);
    labels_kernel<<<(NP + 255) / 256, 256>>>(labels, out);
}